// round 12
// baseline (speedup 1.0000x reference)
#include <cuda_runtime.h>
#include <cstdint>
#include <cstddef>

// FlowNetC correlation: out[b, dy*9+dx, y, x] = (1/C) * sum_c in1[b,c,y,x] * in2[b,c,y+dy-4,x+dx-4]
// Shapes fixed: C=256, H=96, W=128, 81 displacement channels.
// R11: 8-wide x-strips per thread + packed fma.rn.f32x2 + 2 CTAs/SM + bank-conflict padding.

#define C_CH 256
#define H_IN 96
#define W_IN 128
#define ND   9
#define MD   4
#define TY   8
#define TX   32
#define CK   8
#define SY   (TY + 2*MD)          // 16 haloed rows of in2
#define S1W  36                   // padded in1 row stride (floats), 36%32=4 -> conflict-free
#define S2W  44                   // padded in2 row stride (floats), 44%32=12 -> conflict-free
#define NTHREADS 288              // 4 x-octets * 8 rows * 9 dy  (warp == one dyi)
#define S1_FLOATS (CK*TY*S1W)     // 2304
#define S2_FLOATS (CK*SY*S2W)     // 5632
#define BUF_FLOATS (S1_FLOATS + S2_FLOATS)   // 7936
#define SMEM_BYTES (2*BUF_FLOATS*4)          // 63488, double buffered; x2 CTAs = 124KB/SM

__device__ __forceinline__ void cp_async16(uint32_t saddr, const float* gsrc, int src_bytes) {
    asm volatile("cp.async.cg.shared.global [%0], [%1], 16, %2;\n"
                 :: "r"(saddr), "l"(gsrc), "r"(src_bytes));
}
__device__ __forceinline__ void cp_commit() {
    asm volatile("cp.async.commit_group;\n" ::: "memory");
}
__device__ __forceinline__ void cp_wait1() {
    asm volatile("cp.async.wait_group 1;\n" ::: "memory");
}

__device__ __forceinline__ uint64_t pk(float lo, float hi) {
    uint64_t r;
    asm("mov.b64 %0, {%1, %2};" : "=l"(r) : "f"(lo), "f"(hi));
    return r;
}
__device__ __forceinline__ void upk(uint64_t p, float& lo, float& hi) {
    asm("mov.b64 {%0, %1}, %2;" : "=f"(lo), "=f"(hi) : "l"(p));
}
__device__ __forceinline__ void ffma2(uint64_t& d, uint64_t a, uint64_t b) {
    asm("fma.rn.f32x2 %0, %1, %2, %0;" : "+l"(d) : "l"(a), "l"(b));
}

__device__ __forceinline__ void issue_stage(uint32_t smem_base, int buf, int c0,
                                            const float* __restrict__ in1b,
                                            const float* __restrict__ in2b,
                                            int ty0, int tx0, int tid) {
    uint32_t s1a = smem_base + (uint32_t)buf * (BUF_FLOATS * 4);
    uint32_t s2a = s1a + S1_FLOATS * 4;

    // in1 tile: CK x TY x TX (stored with S1W-padded rows). 512 float4s, in bounds.
    #pragma unroll 1
    for (int i = tid; i < CK * TY * (TX / 4); i += NTHREADS) {
        int col4 = i & 7;           // 8 float4 per 32-float row
        int row  = (i >> 3) & 7;    // TY
        int cc   = i >> 6;          // CK
        const float* src = in1b + ((size_t)(c0 + cc) * H_IN + (ty0 + row)) * W_IN
                                + tx0 + col4 * 4;
        cp_async16(s1a + (uint32_t)(cc * (TY * S1W * 4) + row * (S1W * 4) + col4 * 16),
                   src, 16);
    }
    // in2 haloed tile: CK x SY x 40 data floats (S2W-padded rows). 1280 float4s.
    // OOB float4s are fully in or fully out (W%4==0, MD==4) -> src-size 0 zero-fills.
    #pragma unroll 1
    for (int i = tid; i < CK * SY * 10; i += NTHREADS) {
        int col4 = i % 10;
        int row  = (i / 10) % SY;
        int cc   = i / (10 * SY);
        int gx = tx0 + col4 * 4 - MD;
        int gy = ty0 + row - MD;
        bool ok = (gy >= 0) & (gy < H_IN) & (gx >= 0) & (gx <= W_IN - 4);
        const float* src = in2b + ((size_t)(c0 + cc) * H_IN + (ok ? gy : 0)) * W_IN
                                + (ok ? gx : 0);
        cp_async16(s2a + (uint32_t)(cc * (SY * S2W * 4) + row * (S2W * 4) + col4 * 16),
                   src, ok ? 16 : 0);
    }
}

__global__ void __launch_bounds__(NTHREADS, 2)
Correlation_72164040507827_kernel(const float* __restrict__ in1,
                                  const float* __restrict__ in2,
                                  float* __restrict__ out) {
    extern __shared__ float smem[];
    const int tid = threadIdx.x;
    const int b   = blockIdx.z;
    const int ty0 = blockIdx.y * TY;
    const int tx0 = blockIdx.x * TX;

    // warp = one dyi; lane: qy = rows, qx = x-octet
    const int dyi = tid >> 5;      // 0..8
    const int l   = tid & 31;
    const int qy  = l >> 2;        // 0..7
    const int qx  = l & 3;         // 0..3  (8-wide x strip)

    uint64_t acc2[ND][4];          // 9 dx * 4 f32x2 pairs (x pairs within octet)
    #pragma unroll
    for (int d = 0; d < ND; ++d)
        #pragma unroll
        for (int j = 0; j < 4; ++j) acc2[d][j] = 0ull;

    const float* in1b = in1 + (size_t)b * C_CH * (H_IN * W_IN);
    const float* in2b = in2 + (size_t)b * C_CH * (H_IN * W_IN);

    uint32_t smem_base = (uint32_t)__cvta_generic_to_shared(smem);

    issue_stage(smem_base, 0, 0, in1b, in2b, ty0, tx0, tid);
    cp_commit();

    const int s1off = qy * S1W + qx * 8;
    const int s2off = (qy + dyi) * S2W + qx * 8;

    const int nChunks = C_CH / CK;  // 32
    #pragma unroll 1
    for (int k = 0; k < nChunks; ++k) {
        if (k + 1 < nChunks)
            issue_stage(smem_base, (k + 1) & 1, (k + 1) * CK, in1b, in2b, ty0, tx0, tid);
        cp_commit();            // (possibly empty) group keeps wait_group accounting uniform
        cp_wait1();             // stage k resident
        __syncthreads();

        const float* buf = smem + (size_t)(k & 1) * BUF_FLOATS;
        const float* s1c = buf + s1off;
        const float* s2c = buf + S1_FLOATS + s2off;

        #pragma unroll
        for (int cc = 0; cc < CK; ++cc) {
            float4 a0 = *(const float4*)(s1c);
            float4 a1 = *(const float4*)(s1c + 4);
            float4 r0 = *(const float4*)(s2c);
            float4 r1 = *(const float4*)(s2c + 4);
            float4 r2 = *(const float4*)(s2c + 8);
            float4 r3 = *(const float4*)(s2c + 12);
            s1c += TY * S1W;
            s2c += SY * S2W;

            uint64_t A[4]  = { pk(a0.x, a0.y), pk(a0.z, a0.w),
                               pk(a1.x, a1.y), pk(a1.z, a1.w) };
            // aligned in2 pairs (free: adjacent float4 lanes)
            uint64_t PA[8] = { pk(r0.x, r0.y), pk(r0.z, r0.w),
                               pk(r1.x, r1.y), pk(r1.z, r1.w),
                               pk(r2.x, r2.y), pk(r2.z, r2.w),
                               pk(r3.x, r3.y), pk(r3.z, r3.w) };
            // misaligned (odd-dx) pairs
            uint64_t PM[7] = { pk(r0.y, r0.z), pk(r0.w, r1.x),
                               pk(r1.y, r1.z), pk(r1.w, r2.x),
                               pk(r2.y, r2.z), pk(r2.w, r3.x),
                               pk(r3.y, r3.z) };

            #pragma unroll
            for (int dx = 0; dx < ND; ++dx) {
                #pragma unroll
                for (int xp = 0; xp < 4; ++xp) {
                    uint64_t bb = (dx & 1) ? PM[xp + (dx >> 1)]
                                           : PA[xp + (dx >> 1)];
                    ffma2(acc2[dx][xp], A[xp], bb);
                }
            }
        }
        __syncthreads();  // buffer (k&1) fully consumed before refill at k+1
    }

    // Epilogue: normalize, unpack, store 2 float4s per dx. Coalesced per warp.
    const float scale = 1.0f / (float)C_CH;
    const int y   = ty0 + qy;
    const int x0g = tx0 + qx * 8;
    #pragma unroll
    for (int dx = 0; dx < ND; ++dx) {
        float v[8];
        #pragma unroll
        for (int xp = 0; xp < 4; ++xp) {
            float lo, hi;
            upk(acc2[dx][xp], lo, hi);
            v[2 * xp]     = lo * scale;
            v[2 * xp + 1] = hi * scale;
        }
        size_t o = (((size_t)b * (ND * ND) + dyi * ND + dx) * H_IN + y) * W_IN + x0g;
        *(float4*)(out + o)     = make_float4(v[0], v[1], v[2], v[3]);
        *(float4*)(out + o + 4) = make_float4(v[4], v[5], v[6], v[7]);
    }
}

extern "C" void kernel_launch(void* const* d_in, const int* in_sizes, int n_in,
                              void* d_out, int out_size) {
    const float* in1 = (const float*)d_in[0];
    const float* in2 = (const float*)d_in[1];
    float* out = (float*)d_out;

    int B = in_sizes[0] / (C_CH * H_IN * W_IN);

    static bool attr_set = false;
    if (!attr_set) {
        cudaFuncSetAttribute(Correlation_72164040507827_kernel,
                             cudaFuncAttributeMaxDynamicSharedMemorySize, SMEM_BYTES);
        attr_set = true;
    }

    dim3 grid(W_IN / TX, H_IN / TY, B);  // 4 x 12 x B
    Correlation_72164040507827_kernel<<<grid, NTHREADS, SMEM_BYTES>>>(in1, in2, out);
}

// round 15
// speedup vs baseline: 1.0511x; 1.0511x over previous
#include <cuda_runtime.h>
#include <cstdint>
#include <cstddef>

// FlowNetC correlation: out[b, dy*9+dx, y, x] = (1/C) * sum_c in1[b,c,y,x] * in2[b,c,y+dy-4,x+dx-4]
// Shapes fixed: C=256, H=96, W=128, 81 displacement channels.
// R13: 8-wide strips; HYBRID inner loop: even-dx via fma.rn.f32x2 on naturally aligned
// register pairs (double2 SMEM loads, zero packing), odd-dx via scalar FFMA on free
// register-half extraction. 2 CTAs/SM, bank-conflict padded SMEM, cp.async double buffer.

#define C_CH 256
#define H_IN 96
#define W_IN 128
#define ND   9
#define MD   4
#define TY   8
#define TX   32
#define CK   8
#define SY   (TY + 2*MD)          // 16 haloed rows of in2
#define S1W  36                   // padded in1 row stride (floats); 36%32=4 -> conflict-free
#define S2W  44                   // padded in2 row stride (floats); 44%32=12 -> conflict-free
#define NTHREADS 288              // 4 x-octets * 8 rows * 9 dy  (warp == one dyi)
#define S1_FLOATS (CK*TY*S1W)     // 2304
#define S2_FLOATS (CK*SY*S2W)     // 5632
#define BUF_FLOATS (S1_FLOATS + S2_FLOATS)   // 7936
#define SMEM_BYTES (2*BUF_FLOATS*4)          // 63488; x2 CTAs = 124KB/SM (fits 228KB)

__device__ __forceinline__ void cp_async16(uint32_t saddr, const float* gsrc, int src_bytes) {
    asm volatile("cp.async.cg.shared.global [%0], [%1], 16, %2;\n"
                 :: "r"(saddr), "l"(gsrc), "r"(src_bytes));
}
__device__ __forceinline__ void cp_commit() {
    asm volatile("cp.async.commit_group;\n" ::: "memory");
}
__device__ __forceinline__ void cp_wait1() {
    asm volatile("cp.async.wait_group 1;\n" ::: "memory");
}

// Packed f32x2 FMA on double-carried register pairs. The mov.b64 copies are
// pair->pair (no half repacking) so ptxas coalesces them into direct register use.
__device__ __forceinline__ void ffma2(double& acc, double a, double b) {
    asm("{\n\t"
        ".reg .b64 ta, tb, tc;\n\t"
        "mov.b64 ta, %1;\n\t"
        "mov.b64 tb, %2;\n\t"
        "mov.b64 tc, %0;\n\t"
        "fma.rn.f32x2 tc, ta, tb, tc;\n\t"
        "mov.b64 %0, tc;\n\t"
        "}" : "+d"(acc) : "d"(a), "d"(b));
}
__device__ __forceinline__ float lo32(double d) { return __int_as_float(__double2loint(d)); }
__device__ __forceinline__ float hi32(double d) { return __int_as_float(__double2hiint(d)); }

__device__ __forceinline__ void issue_stage(uint32_t smem_base, int buf, int c0,
                                            const float* __restrict__ in1b,
                                            const float* __restrict__ in2b,
                                            int ty0, int tx0, int tid) {
    uint32_t s1a = smem_base + (uint32_t)buf * (BUF_FLOATS * 4);
    uint32_t s2a = s1a + S1_FLOATS * 4;

    // in1 tile: CK x TY x TX (S1W-padded rows). 512 float4s, always in bounds.
    #pragma unroll 1
    for (int i = tid; i < CK * TY * (TX / 4); i += NTHREADS) {
        int col4 = i & 7;
        int row  = (i >> 3) & 7;
        int cc   = i >> 6;
        const float* src = in1b + ((size_t)(c0 + cc) * H_IN + (ty0 + row)) * W_IN
                                + tx0 + col4 * 4;
        cp_async16(s1a + (uint32_t)(cc * (TY * S1W * 4) + row * (S1W * 4) + col4 * 16),
                   src, 16);
    }
    // in2 haloed tile: CK x SY x 40 data floats (S2W-padded rows). OOB float4s are
    // fully in or fully out (W%4==0, MD==4) -> src-size 0 zero-fills.
    #pragma unroll 1
    for (int i = tid; i < CK * SY * 10; i += NTHREADS) {
        int col4 = i % 10;
        int row  = (i / 10) % SY;
        int cc   = i / (10 * SY);
        int gx = tx0 + col4 * 4 - MD;
        int gy = ty0 + row - MD;
        bool ok = (gy >= 0) & (gy < H_IN) & (gx >= 0) & (gx <= W_IN - 4);
        const float* src = in2b + ((size_t)(c0 + cc) * H_IN + (ok ? gy : 0)) * W_IN
                                + (ok ? gx : 0);
        cp_async16(s2a + (uint32_t)(cc * (SY * S2W * 4) + row * (S2W * 4) + col4 * 16),
                   src, ok ? 16 : 0);
    }
}

__global__ void __launch_bounds__(NTHREADS, 2)
Correlation_72164040507827_kernel(const float* __restrict__ in1,
                                  const float* __restrict__ in2,
                                  float* __restrict__ out) {
    extern __shared__ float smem[];
    const int tid = threadIdx.x;
    const int b   = blockIdx.z;
    const int ty0 = blockIdx.y * TY;
    const int tx0 = blockIdx.x * TX;

    const int dyi = tid >> 5;      // warp = one dyi, 0..8
    const int l   = tid & 31;
    const int qy  = l >> 2;        // 0..7 rows
    const int qx  = l & 3;         // 0..3 x-octets (8-wide strip)

    double accE[5][4];             // even dx (0,2,4,6,8): f32x2 pairs (x pairs 0..3)
    float  accO[4][8];             // odd dx (1,3,5,7): scalar
    #pragma unroll
    for (int e = 0; e < 5; ++e)
        #pragma unroll
        for (int j = 0; j < 4; ++j) accE[e][j] = 0.0;
    #pragma unroll
    for (int o = 0; o < 4; ++o)
        #pragma unroll
        for (int j = 0; j < 8; ++j) accO[o][j] = 0.0f;

    const float* in1b = in1 + (size_t)b * C_CH * (H_IN * W_IN);
    const float* in2b = in2 + (size_t)b * C_CH * (H_IN * W_IN);

    uint32_t smem_base = (uint32_t)__cvta_generic_to_shared(smem);

    issue_stage(smem_base, 0, 0, in1b, in2b, ty0, tx0, tid);
    cp_commit();

    const int s1off = qy * S1W + qx * 8;               // 16B aligned (qx*32B)
    const int s2off = (qy + dyi) * S2W + qx * 8;       // rows 176B -> 16B aligned

    const int nChunks = C_CH / CK;  // 32
    #pragma unroll 1
    for (int k = 0; k < nChunks; ++k) {
        if (k + 1 < nChunks)
            issue_stage(smem_base, (k + 1) & 1, (k + 1) * CK, in1b, in2b, ty0, tx0, tid);
        cp_commit();            // (possibly empty) group keeps wait_group accounting uniform
        cp_wait1();             // stage k resident
        __syncthreads();

        const float* buf = smem + (size_t)(k & 1) * BUF_FLOATS;
        const float* s1c = buf + s1off;
        const float* s2c = buf + S1_FLOATS + s2off;

        #pragma unroll
        for (int cc = 0; cc < CK; ++cc) {
            // A: 8 in1 floats = 4 aligned pairs. P: 16 in2 floats = 8 aligned pairs.
            double2 a01 = *(const double2*)(s1c);
            double2 a23 = *(const double2*)(s1c + 4);
            double2 p01 = *(const double2*)(s2c);
            double2 p23 = *(const double2*)(s2c + 4);
            double2 p45 = *(const double2*)(s2c + 8);
            double2 p67 = *(const double2*)(s2c + 12);
            s1c += TY * S1W;
            s2c += SY * S2W;

            double A[4] = { a01.x, a01.y, a23.x, a23.y };
            double P[8] = { p01.x, p01.y, p23.x, p23.y,
                            p45.x, p45.y, p67.x, p67.y };

            // even dx = 2e: pair (2xp,2xp+1) needs r[2xp+2e .. 2xp+2e+1] = P[xp+e]
            #pragma unroll
            for (int e = 0; e < 5; ++e)
                #pragma unroll
                for (int xp = 0; xp < 4; ++xp)
                    ffma2(accE[e][xp], A[xp], P[xp + e]);

            // odd dx: scalar on free register halves
            float af[8], rf[16];
            #pragma unroll
            for (int j = 0; j < 4; ++j) { af[2*j] = lo32(A[j]); af[2*j+1] = hi32(A[j]); }
            #pragma unroll
            for (int j = 0; j < 8; ++j) { rf[2*j] = lo32(P[j]); rf[2*j+1] = hi32(P[j]); }
            #pragma unroll
            for (int o = 0; o < 4; ++o) {
                const int dx = 2 * o + 1;
                #pragma unroll
                for (int j = 0; j < 8; ++j)
                    accO[o][j] += af[j] * rf[j + dx];
            }
        }
        __syncthreads();  // buffer (k&1) fully consumed before refill at k+1
    }

    // Epilogue: normalize and store 2 float4s per dx (coalesced within warp).
    const float scale = 1.0f / (float)C_CH;
    const int y   = ty0 + qy;
    const int x0g = tx0 + qx * 8;
    #pragma unroll
    for (int dx = 0; dx < ND; ++dx) {
        float v[8];
        if ((dx & 1) == 0) {
            const int e = dx >> 1;
            #pragma unroll
            for (int xp = 0; xp < 4; ++xp) {
                v[2*xp]   = lo32(accE[e][xp]) * scale;
                v[2*xp+1] = hi32(accE[e][xp]) * scale;
            }
        } else {
            const int o = dx >> 1;
            #pragma unroll
            for (int j = 0; j < 8; ++j) v[j] = accO[o][j] * scale;
        }
        size_t ofs = (((size_t)b * (ND * ND) + dyi * ND + dx) * H_IN + y) * W_IN + x0g;
        *(float4*)(out + ofs)     = make_float4(v[0], v[1], v[2], v[3]);
        *(float4*)(out + ofs + 4) = make_float4(v[4], v[5], v[6], v[7]);
    }
}

extern "C" void kernel_launch(void* const* d_in, const int* in_sizes, int n_in,
                              void* d_out, int out_size) {
    const float* in1 = (const float*)d_in[0];
    const float* in2 = (const float*)d_in[1];
    float* out = (float*)d_out;

    int B = in_sizes[0] / (C_CH * H_IN * W_IN);

    static bool attr_set = false;
    if (!attr_set) {
        cudaFuncSetAttribute(Correlation_72164040507827_kernel,
                             cudaFuncAttributeMaxDynamicSharedMemorySize, SMEM_BYTES);
        attr_set = true;
    }

    dim3 grid(W_IN / TX, H_IN / TY, B);  // 4 x 12 x B
    Correlation_72164040507827_kernel<<<grid, NTHREADS, SMEM_BYTES>>>(in1, in2, out);
}